// round 7
// baseline (speedup 1.0000x reference)
#include <cuda_runtime.h>
#include <cuda_bf16.h>
#include <math.h>
#include <stdint.h>

#define B_ 4
#define N_ 4096
#define D_ 1024
#define E_ 8
#define M_ 512   // N/E tokens per expert

// ---------------- scratch (device globals; no allocation allowed) ----------------
__device__ float g_t[B_ * N_ * E_];         // log(clamp(gate logits)) [b][n][e], read-only after k1
__device__ float g_r[B_ * N_];              // sinkhorn row (token) offsets
__device__ float g_c[B_ * E_];              // sinkhorn col (expert) offsets
__device__ int   g_topk_idx[B_ * E_ * M_];  // sorted token indices per (b,e), descending gate
__device__ float g_topk_val[B_ * E_ * M_];  // matching gate values
__device__ int   g_winner[B_ * N_];         // per-token winning key m*E+e (last-wins), -1 if unrouted

// tf32 (RNA-rounded) operands for the tensor-core GEMM
__device__ float g_xt[B_ * N_ * D_];   // tf32(x)
__device__ float g_wt[E_ * D_ * D_];   // tf32(W^T): [e][f][k]

__device__ __forceinline__ uint32_t smem_u32(const void* p) {
    uint32_t a;
    asm("{ .reg .u64 t; cvta.to.shared.u64 t, %1; cvt.u32.u64 %0, t; }" : "=r"(a) : "l"(p));
    return a;
}
__device__ __forceinline__ void cp16(uint32_t dst, const void* src) {
    asm volatile("cp.async.cg.shared.global [%0], [%1], 16;" :: "r"(dst), "l"(src));
}
__device__ __forceinline__ uint32_t f2tf32(float f) {
    uint32_t u;
    asm("cvt.rna.tf32.f32 %0, %1;" : "=r"(u) : "f"(f));
    return u;
}
__device__ __forceinline__ void mma_tf32(float* d, const uint32_t* a, const uint32_t* b) {
    asm volatile(
        "mma.sync.aligned.m16n8k8.row.col.f32.tf32.tf32.f32 "
        "{%0,%1,%2,%3}, {%4,%5,%6,%7}, {%8,%9}, {%0,%1,%2,%3};"
        : "+f"(d[0]), "+f"(d[1]), "+f"(d[2]), "+f"(d[3])
        : "r"(a[0]), "r"(a[1]), "r"(a[2]), "r"(a[3]), "r"(b[0]), "r"(b[1]));
}

// ========== k1: gate logits (+log clamp) + convert x->tf32 + convert W->W^T tf32 + winner init ==========
__global__ __launch_bounds__(256) void gate_fused_kernel(
    const float* __restrict__ x, const float* __restrict__ gw, const float* __restrict__ w) {
    __shared__ float sw[E_ * D_];   // gate weights transposed [e][d]
    __shared__ float wt[32][33];    // W transpose tile

    int tid = threadIdx.x;
    for (int i = tid; i < D_ * E_; i += 256) {
        int d = i / E_, e = i % E_;
        sw[e * D_ + d] = gw[i];
    }
    if (blockIdx.x < (B_ * N_) / 256)
        g_winner[blockIdx.x * 256 + tid] = -1;
    __syncthreads();

    // gate logits + x conversion: 8 warps, one token row each
    int warp = tid >> 5, lane = tid & 31;
    int row = blockIdx.x * 8 + warp;
    {
        const float* xr = x + (size_t)row * D_;
        uint32_t* xo = (uint32_t*)(g_xt + (size_t)row * D_);
        float acc[E_];
#pragma unroll
        for (int e = 0; e < E_; e++) acc[e] = 0.f;
        for (int d = lane; d < D_; d += 32) {
            float xv = xr[d];
            xo[d] = f2tf32(xv);
#pragma unroll
            for (int e = 0; e < E_; e++) acc[e] += xv * sw[e * D_ + d];
        }
#pragma unroll
        for (int e = 0; e < E_; e++) {
#pragma unroll
            for (int off = 16; off; off >>= 1)
                acc[e] += __shfl_xor_sync(0xFFFFFFFFu, acc[e], off);
        }
        if (lane == 0) {
#pragma unroll
            for (int e = 0; e < E_; e++)
                g_t[(size_t)row * E_ + e] = logf(fmaxf(acc[e], 1e-6f));
        }
    }

    // W transpose + tf32: 4 tiles of 32x32 per block (8192 tiles total)
    int tx = tid & 31, tyy = tid >> 5;  // 32 x 8
#pragma unroll 1
    for (int t = 0; t < 4; t++) {
        int tile = blockIdx.x * 4 + t;
        int e = tile >> 10;
        int rem = tile & 1023;
        int k0 = (rem >> 5) * 32, f0 = (rem & 31) * 32;
        const float* wb = w + (size_t)e * D_ * D_;
        __syncthreads();
#pragma unroll
        for (int j = 0; j < 32; j += 8)
            wt[tyy + j][tx] = wb[(size_t)(k0 + tyy + j) * D_ + f0 + tx];
        __syncthreads();
#pragma unroll
        for (int j = 0; j < 32; j += 8) {
            size_t o = (size_t)e * D_ * D_ + (size_t)(f0 + tyy + j) * D_ + k0 + tx;
            ((uint32_t*)g_wt)[o] = f2tf32(wt[tx][tyy + j]);
        }
    }
}

// ========== k2: Sinkhorn u/v form: c_e = LSE_n(t0 - r), r_n = LSE_e(t0 - c) ==========
#define SROW 4100   // padded row pitch (floats) -> conflict-free both phases
__global__ __launch_bounds__(1024) void sinkhorn_kernel() {
    extern __shared__ float sm[];          // st[8][SROW] then sr[4096]
    float* st = sm;
    float* sr = sm + 8 * SROW;
    __shared__ float s_pm[32], s_ps[32], s_c[E_];

    int b = blockIdx.x, tid = threadIdx.x;
    const float* tb = g_t + (size_t)b * N_ * E_;
    for (int i = tid; i < N_ * E_; i += 1024) {
        int n = i >> 3, e = i & 7;
        st[e * SROW + n] = tb[i];
    }
    for (int n = tid; n < N_; n += 1024) sr[n] = 0.f;
    __syncthreads();

    int warp = tid >> 5, lane = tid & 31;
    int e_w = warp & 7, seg = warp >> 3;   // 4 warps per expert, 1024-token segments

    for (int it = 0; it < 8; it++) {
        // ---- col phase: c_e = LSE_n(st[e][n] - sr[n]) ----
        int base = seg * 1024 + lane;
        const float* se = st + e_w * SROW;
        float m = -INFINITY;
#pragma unroll 8
        for (int k = 0; k < 32; k++) m = fmaxf(m, se[base + k * 32] - sr[base + k * 32]);
#pragma unroll
        for (int off = 16; off; off >>= 1)
            m = fmaxf(m, __shfl_xor_sync(0xFFFFFFFFu, m, off));
        float s = 0.f;
#pragma unroll 8
        for (int k = 0; k < 32; k++) s += __expf(se[base + k * 32] - sr[base + k * 32] - m);
#pragma unroll
        for (int off = 16; off; off >>= 1)
            s += __shfl_xor_sync(0xFFFFFFFFu, s, off);
        if (lane == 0) { s_pm[warp] = m; s_ps[warp] = s; }
        __syncthreads();
        if (tid < E_) {
            float mm = fmaxf(fmaxf(s_pm[tid], s_pm[8 + tid]), fmaxf(s_pm[16 + tid], s_pm[24 + tid]));
            float ss = 0.f;
#pragma unroll
            for (int q = 0; q < 4; q++) ss += s_ps[q * 8 + tid] * __expf(s_pm[q * 8 + tid] - mm);
            s_c[tid] = mm + __logf(ss);
        }
        __syncthreads();
        // ---- row phase: sr[n] = LSE_e(st[e][n] - c_e) ----
        float c0 = s_c[0], c1 = s_c[1], c2 = s_c[2], c3 = s_c[3];
        float c4 = s_c[4], c5 = s_c[5], c6 = s_c[6], c7 = s_c[7];
#pragma unroll
        for (int q = 0; q < 4; q++) {
            int n = tid + q * 1024;
            float v0 = st[0 * SROW + n] - c0, v1 = st[1 * SROW + n] - c1;
            float v2 = st[2 * SROW + n] - c2, v3 = st[3 * SROW + n] - c3;
            float v4 = st[4 * SROW + n] - c4, v5 = st[5 * SROW + n] - c5;
            float v6 = st[6 * SROW + n] - c6, v7 = st[7 * SROW + n] - c7;
            float mm = fmaxf(fmaxf(fmaxf(v0, v1), fmaxf(v2, v3)),
                             fmaxf(fmaxf(v4, v5), fmaxf(v6, v7)));
            float ss = __expf(v0 - mm) + __expf(v1 - mm) + __expf(v2 - mm) + __expf(v3 - mm)
                     + __expf(v4 - mm) + __expf(v5 - mm) + __expf(v6 - mm) + __expf(v7 - mm);
            sr[n] = mm + __logf(ss);
        }
        __syncthreads();
    }
    for (int n = tid; n < N_; n += 1024) g_r[b * N_ + n] = sr[n];
    if (tid < E_) g_c[b * E_ + tid] = s_c[tid];
}

// ========== k3: top-512 sort per (b,e) + winner scatter ==========
__global__ __launch_bounds__(1024) void topk_winner_kernel() {
    __shared__ unsigned long long keys[N_];
    int b = blockIdx.x >> 3, e = blockIdx.x & 7;
    int tid = threadIdx.x;
    const float* tb = g_t + (size_t)b * N_ * E_ + e;   // stride E_
    const float* rb = g_r + (size_t)b * N_;
    float ce = g_c[b * E_ + e];

    for (int i = tid; i < N_; i += 1024) {
        float v = tb[(size_t)i * E_] - rb[i];
        unsigned int u = __float_as_uint(v);
        u = (u & 0x80000000u) ? ~u : (u | 0x80000000u);
        keys[i] = ((unsigned long long)u << 32) | (unsigned int)(N_ - 1 - i);
    }
    __syncthreads();
    for (int k = 2; k <= N_; k <<= 1) {
        for (int j = k >> 1; j > 0; j >>= 1) {
            for (int i = tid; i < N_; i += 1024) {
                int l = i ^ j;
                if (l > i) {
                    unsigned long long a = keys[i], c = keys[l];
                    bool desc = ((i & k) == 0);
                    if (desc ? (a < c) : (a > c)) { keys[i] = c; keys[l] = a; }
                }
            }
            __syncthreads();
        }
    }
    for (int m = tid; m < M_; m += 1024) {
        unsigned long long K = keys[m];
        int n = (N_ - 1) - (int)(unsigned int)(K & 0xFFFFFFFFull);
        int o = (b * E_ + e) * M_ + m;
        g_topk_idx[o] = n;
        g_topk_val[o] = expf(tb[(size_t)n * E_] - rb[n] - ce);
        atomicMax(&g_winner[b * N_ + n], m * E_ + e);   // last-wins over row-major (m,e)
    }
}

// ========== k4: tf32 mma.sync gathered expert GEMM (PROFILED LAUNCH) ==========
// CTA tile 256(m) x 128(f); 8 warps in 4x2 of 64x64; BK=32, triple-buffered cp.async.
#define ROWF 36
#define A_TILE_F (256 * ROWF * 4)        // 36864 B
#define B_TILE_F (128 * ROWF * 4)        // 18432 B
#define STAGE_F (A_TILE_F + B_TILE_F)    // 55296 B

__device__ __forceinline__ void load_stage_t(
    uint32_t sbase, int buf, int k0, int tid,
    const float* __restrict__ xt, const float* __restrict__ wt, const int* s_n)
{
    uint32_t sb = sbase + (uint32_t)buf * STAGE_F;
#pragma unroll
    for (int i = tid; i < 3072; i += 256) {
        uint32_t dst;
        const float* src;
        if (i < 2048) {                       // A: 256 rows x 8 cp16
            int r = i >> 3, cc = i & 7;
            dst = sb + (uint32_t)r * (ROWF * 4) + (uint32_t)cc * 16;
            src = xt + (size_t)s_n[r] * D_ + k0 + cc * 4;
        } else {                              // B: 128 rows x 8 cp16
            int j = i - 2048;
            int r = j >> 3, cc = j & 7;
            dst = sb + A_TILE_F + (uint32_t)r * (ROWF * 4) + (uint32_t)cc * 16;
            src = wt + (size_t)r * D_ + k0 + cc * 4;
        }
        cp16(dst, src);
    }
}

__global__ __launch_bounds__(256) void expert_gemm_mma(float* __restrict__ out) {
    extern __shared__ unsigned char dynsmem[];
    __shared__ int   s_n[256];
    __shared__ float s_v[256];
    __shared__ int   s_w[256];

    int bz = blockIdx.z;  int b = bz >> 3;  int e = bz & 7;
    int m0 = blockIdx.x * 256, f0 = blockIdx.y * 128;
    int tid = threadIdx.x, wid = tid >> 5, lane = tid & 31;
    int wm = wid & 3, wn = wid >> 2;   // warp tile: rows wm*64.., cols wn*64..

    uint32_t sbase = smem_u32(dynsmem);
    const uint32_t* smw = (const uint32_t*)dynsmem;

    {
        int o = bz * M_ + m0 + tid;
        int n = g_topk_idx[o];
        s_n[tid] = n;
        s_v[tid] = g_topk_val[o];
        s_w[tid] = (g_winner[b * N_ + n] == (m0 + tid) * E_ + e) ? 1 : 0;
    }
    __syncthreads();

    const float* xt = g_xt + (size_t)b * N_ * D_;
    const float* wt = g_wt + ((size_t)e * D_ + f0) * D_;

    float d[4][8][4];
#pragma unroll
    for (int i = 0; i < 4; i++)
#pragma unroll
        for (int j = 0; j < 8; j++)
#pragma unroll
            for (int q = 0; q < 4; q++) d[i][j][q] = 0.f;

    load_stage_t(sbase, 0, 0, tid, xt, wt, s_n);
    asm volatile("cp.async.commit_group;" ::: "memory");
    load_stage_t(sbase, 1, 32, tid, xt, wt, s_n);
    asm volatile("cp.async.commit_group;" ::: "memory");
    load_stage_t(sbase, 2, 64, tid, xt, wt, s_n);
    asm volatile("cp.async.commit_group;" ::: "memory");

    int qa = lane >> 2, ma = lane & 3;
    int buf = 0;

#pragma unroll 1
    for (int c = 0; c < 32; c++) {
        if (c >= 30) asm volatile("cp.async.wait_group 0;" ::: "memory");
        else         asm volatile("cp.async.wait_group 2;" ::: "memory");
        __syncthreads();

        const uint32_t* sbA = smw + (size_t)buf * (STAGE_F / 4);
        const uint32_t* sbB = sbA + A_TILE_F / 4;
#pragma unroll
        for (int kk = 0; kk < 32; kk += 8) {
            uint32_t afr[4][4], bfr[8][2];
#pragma unroll
            for (int mt = 0; mt < 4; mt++) {
                int r0 = wm * 64 + mt * 16 + qa;
                afr[mt][0] = sbA[r0 * ROWF + kk + ma];
                afr[mt][1] = sbA[(r0 + 8) * ROWF + kk + ma];
                afr[mt][2] = sbA[r0 * ROWF + kk + ma + 4];
                afr[mt][3] = sbA[(r0 + 8) * ROWF + kk + ma + 4];
            }
#pragma unroll
            for (int nt = 0; nt < 8; nt++) {
                int fc = wn * 64 + nt * 8 + qa;
                bfr[nt][0] = sbB[fc * ROWF + kk + ma];
                bfr[nt][1] = sbB[fc * ROWF + kk + ma + 4];
            }
#pragma unroll
            for (int mt = 0; mt < 4; mt++)
#pragma unroll
                for (int nt = 0; nt < 8; nt++) mma_tf32(d[mt][nt], afr[mt], bfr[nt]);
        }
        __syncthreads();
        if (c < 29) {
            load_stage_t(sbase, buf, (c + 3) * 32, tid, xt, wt, s_n);
            asm volatile("cp.async.commit_group;" ::: "memory");
        }
        buf = (buf == 2) ? 0 : buf + 1;
    }

    // epilogue: scale by gate value, winner-gated scatter
#pragma unroll
    for (int mt = 0; mt < 4; mt++) {
        int rbase = wm * 64 + mt * 16 + qa;
#pragma unroll
        for (int half = 0; half < 2; half++) {
            int r = rbase + half * 8;
            if (s_w[r]) {
                float sv = s_v[r];
                float* orow = out + ((size_t)b * N_ + s_n[r]) * D_ + f0 + wn * 64 + ma * 2;
#pragma unroll
                for (int nt = 0; nt < 8; nt++) {
                    float2 v;
                    v.x = d[mt][nt][half * 2 + 0] * sv;
                    v.y = d[mt][nt][half * 2 + 1] * sv;
                    *(float2*)(orow + nt * 8) = v;
                }
            }
        }
    }
}

// ========== k5: zero only unrouted rows (disjoint from GEMM-written rows) ==========
__global__ void zero_unrouted_kernel(float4* __restrict__ out) {
    int row = blockIdx.x;                 // b*N + n
    if (g_winner[row] >= 0) return;
    out[(size_t)row * (D_ / 4) + threadIdx.x] = make_float4(0.f, 0.f, 0.f, 0.f);
}

// ---------------- launch ----------------
extern "C" void kernel_launch(void* const* d_in, const int* in_sizes, int n_in,
                              void* d_out, int out_size) {
    const float* x       = (const float*)d_in[0];
    const float* gw      = (const float*)d_in[1];
    const float* experts = (const float*)d_in[2];
    float* out = (float*)d_out;

    cudaFuncSetAttribute(sinkhorn_kernel, cudaFuncAttributeMaxDynamicSharedMemorySize,
                         (8 * SROW + N_) * (int)sizeof(float));
    cudaFuncSetAttribute(expert_gemm_mma, cudaFuncAttributeMaxDynamicSharedMemorySize,
                         3 * STAGE_F);

    gate_fused_kernel<<<(B_ * N_) / 8, 256>>>(x, gw, experts);
    sinkhorn_kernel<<<B_, 1024, (8 * SROW + N_) * sizeof(float)>>>();
    topk_winner_kernel<<<B_ * E_, 1024>>>();
    expert_gemm_mma<<<dim3(M_ / 256, D_ / 128, B_ * E_), 256, 3 * STAGE_F>>>(out);
    zero_unrouted_kernel<<<B_ * N_, 256>>>((float4*)out);
}

// round 8
// speedup vs baseline: 1.1581x; 1.1581x over previous
#include <cuda_runtime.h>
#include <cuda_bf16.h>
#include <math.h>
#include <stdint.h>

#define B_ 4
#define N_ 4096
#define D_ 1024
#define E_ 8
#define M_ 512   // N/E tokens per expert

// ---------------- scratch (device globals; no allocation allowed) ----------------
__device__ float g_t[B_ * N_ * E_];         // log(clamp(gate logits)) [b][n][e]
__device__ float g_r[B_ * N_];              // sinkhorn row (token) offsets
__device__ float g_c[B_ * E_];              // sinkhorn col (expert) offsets
__device__ int   g_topk_idx[B_ * E_ * M_];  // sorted token indices per (b,e), descending gate
__device__ float g_topk_val[B_ * E_ * M_];  // matching gate values
__device__ int   g_winner[B_ * N_];         // per-token winning key m*E+e (last-wins), -1 if unrouted

__device__ float g_xt[B_ * N_ * D_];        // tf32(x), RNA-rounded

__device__ __forceinline__ uint32_t smem_u32(const void* p) {
    uint32_t a;
    asm("{ .reg .u64 t; cvta.to.shared.u64 t, %1; cvt.u32.u64 %0, t; }" : "=r"(a) : "l"(p));
    return a;
}
__device__ __forceinline__ void cp16(uint32_t dst, const void* src) {
    asm volatile("cp.async.cg.shared.global [%0], [%1], 16;" :: "r"(dst), "l"(src));
}
__device__ __forceinline__ uint32_t f2tf32(float f) {
    uint32_t u;
    asm("cvt.rna.tf32.f32 %0, %1;" : "=r"(u) : "f"(f));
    return u;
}
__device__ __forceinline__ void mma_tf32(float* d, const uint32_t* a, const uint32_t* b) {
    asm volatile(
        "mma.sync.aligned.m16n8k8.row.col.f32.tf32.tf32.f32 "
        "{%0,%1,%2,%3}, {%4,%5,%6,%7}, {%8,%9}, {%0,%1,%2,%3};"
        : "+f"(d[0]), "+f"(d[1]), "+f"(d[2]), "+f"(d[3])
        : "r"(a[0]), "r"(a[1]), "r"(a[2]), "r"(a[3]), "r"(b[0]), "r"(b[1]));
}

// ========== k1: gate logits (+log clamp) + convert x->tf32 + winner init ==========
__global__ __launch_bounds__(256) void gate_fused_kernel(
    const float* __restrict__ x, const float* __restrict__ gw) {
    __shared__ float sw[E_ * D_];   // gate weights transposed [e][d]
    int tid = threadIdx.x;
    for (int i = tid; i < D_ * E_; i += 256) {
        int d = i / E_, e = i % E_;
        sw[e * D_ + d] = gw[i];
    }
    if (blockIdx.x < (B_ * N_) / 256)
        g_winner[blockIdx.x * 256 + tid] = -1;
    __syncthreads();

    int warp = tid >> 5, lane = tid & 31;
    int row = blockIdx.x * 8 + warp;
    const float* xr = x + (size_t)row * D_;
    uint32_t* xo = (uint32_t*)(g_xt + (size_t)row * D_);
    float acc[E_];
#pragma unroll
    for (int e = 0; e < E_; e++) acc[e] = 0.f;
    for (int d = lane; d < D_; d += 32) {
        float xv = xr[d];
        xo[d] = f2tf32(xv);
#pragma unroll
        for (int e = 0; e < E_; e++) acc[e] += xv * sw[e * D_ + d];
    }
#pragma unroll
    for (int e = 0; e < E_; e++) {
#pragma unroll
        for (int off = 16; off; off >>= 1)
            acc[e] += __shfl_xor_sync(0xFFFFFFFFu, acc[e], off);
    }
    if (lane == 0) {
#pragma unroll
        for (int e = 0; e < E_; e++)
            g_t[(size_t)row * E_ + e] = logf(fmaxf(acc[e], 1e-6f));
    }
}

// ========== k2: Sinkhorn u/v form: c_e = LSE_n(t0 - r), r_n = LSE_e(t0 - c) ==========
#define SROW 4100
__global__ __launch_bounds__(1024) void sinkhorn_kernel() {
    extern __shared__ float sm[];          // st[8][SROW] then sr[4096]
    float* st = sm;
    float* sr = sm + 8 * SROW;
    __shared__ float s_pm[32], s_ps[32], s_c[E_];

    int b = blockIdx.x, tid = threadIdx.x;
    const float* tb = g_t + (size_t)b * N_ * E_;
    for (int i = tid; i < N_ * E_; i += 1024) {
        int n = i >> 3, e = i & 7;
        st[e * SROW + n] = tb[i];
    }
    for (int n = tid; n < N_; n += 1024) sr[n] = 0.f;
    __syncthreads();

    int warp = tid >> 5, lane = tid & 31;
    int e_w = warp & 7, seg = warp >> 3;

    for (int it = 0; it < 8; it++) {
        int base = seg * 1024 + lane;
        const float* se = st + e_w * SROW;
        float m = -INFINITY;
#pragma unroll 8
        for (int k = 0; k < 32; k++) m = fmaxf(m, se[base + k * 32] - sr[base + k * 32]);
#pragma unroll
        for (int off = 16; off; off >>= 1)
            m = fmaxf(m, __shfl_xor_sync(0xFFFFFFFFu, m, off));
        float s = 0.f;
#pragma unroll 8
        for (int k = 0; k < 32; k++) s += __expf(se[base + k * 32] - sr[base + k * 32] - m);
#pragma unroll
        for (int off = 16; off; off >>= 1)
            s += __shfl_xor_sync(0xFFFFFFFFu, s, off);
        if (lane == 0) { s_pm[warp] = m; s_ps[warp] = s; }
        __syncthreads();
        if (tid < E_) {
            float mm = fmaxf(fmaxf(s_pm[tid], s_pm[8 + tid]), fmaxf(s_pm[16 + tid], s_pm[24 + tid]));
            float ss = 0.f;
#pragma unroll
            for (int q = 0; q < 4; q++) ss += s_ps[q * 8 + tid] * __expf(s_pm[q * 8 + tid] - mm);
            s_c[tid] = mm + __logf(ss);
        }
        __syncthreads();
        float c0 = s_c[0], c1 = s_c[1], c2 = s_c[2], c3 = s_c[3];
        float c4 = s_c[4], c5 = s_c[5], c6 = s_c[6], c7 = s_c[7];
#pragma unroll
        for (int q = 0; q < 4; q++) {
            int n = tid + q * 1024;
            float v0 = st[0 * SROW + n] - c0, v1 = st[1 * SROW + n] - c1;
            float v2 = st[2 * SROW + n] - c2, v3 = st[3 * SROW + n] - c3;
            float v4 = st[4 * SROW + n] - c4, v5 = st[5 * SROW + n] - c5;
            float v6 = st[6 * SROW + n] - c6, v7 = st[7 * SROW + n] - c7;
            float mm = fmaxf(fmaxf(fmaxf(v0, v1), fmaxf(v2, v3)),
                             fmaxf(fmaxf(v4, v5), fmaxf(v6, v7)));
            float ss = __expf(v0 - mm) + __expf(v1 - mm) + __expf(v2 - mm) + __expf(v3 - mm)
                     + __expf(v4 - mm) + __expf(v5 - mm) + __expf(v6 - mm) + __expf(v7 - mm);
            sr[n] = mm + __logf(ss);
        }
        __syncthreads();
    }
    for (int n = tid; n < N_; n += 1024) g_r[b * N_ + n] = sr[n];
    if (tid < E_) g_c[b * E_ + tid] = s_c[tid];
}

// ========== k3: top-512 sort per (b,e) + winner scatter ==========
__global__ __launch_bounds__(1024) void topk_winner_kernel() {
    __shared__ unsigned long long keys[N_];
    int b = blockIdx.x >> 3, e = blockIdx.x & 7;
    int tid = threadIdx.x;
    const float* tb = g_t + (size_t)b * N_ * E_ + e;
    const float* rb = g_r + (size_t)b * N_;
    float ce = g_c[b * E_ + e];

    for (int i = tid; i < N_; i += 1024) {
        float v = tb[(size_t)i * E_] - rb[i];
        unsigned int u = __float_as_uint(v);
        u = (u & 0x80000000u) ? ~u : (u | 0x80000000u);
        keys[i] = ((unsigned long long)u << 32) | (unsigned int)(N_ - 1 - i);
    }
    __syncthreads();
    for (int k = 2; k <= N_; k <<= 1) {
        for (int j = k >> 1; j > 0; j >>= 1) {
            for (int i = tid; i < N_; i += 1024) {
                int l = i ^ j;
                if (l > i) {
                    unsigned long long a = keys[i], c = keys[l];
                    bool desc = ((i & k) == 0);
                    if (desc ? (a < c) : (a > c)) { keys[i] = c; keys[l] = a; }
                }
            }
            __syncthreads();
        }
    }
    for (int m = tid; m < M_; m += 1024) {
        unsigned long long K = keys[m];
        int n = (N_ - 1) - (int)(unsigned int)(K & 0xFFFFFFFFull);
        int o = (b * E_ + e) * M_ + m;
        g_topk_idx[o] = n;
        g_topk_val[o] = expf(tb[(size_t)n * E_] - rb[n] - ce);
        atomicMax(&g_winner[b * N_ + n], m * E_ + e);
    }
}

// ========== k4: tf32 mma.sync gathered expert GEMM (PROFILED LAUNCH) ==========
// CTA tile 128(m) x 128(f); 8 warps in 2x4 of 64x32; BK=32, 3-stage cp.async.
// A smem: [m-row][k], pitch 36 floats. B smem: [k-row][f], pitch 136 floats
// (direct from experts — no transpose; fp32->tf32 by HW truncation on B).
#define ROWF 36
#define BF   136
#define A_TILE_F (128 * ROWF * 4)        // 18432 B
#define B_TILE_F (32 * BF * 4)           // 17408 B
#define STAGE_F (A_TILE_F + B_TILE_F)    // 35840 B

__device__ __forceinline__ void load_stage_t(
    uint32_t sbase, int buf, int k0, int tid,
    const float* __restrict__ xt, const float* __restrict__ wb, const int* s_n)
{
    uint32_t sb = sbase + (uint32_t)buf * STAGE_F;
#pragma unroll
    for (int i = tid; i < 2048; i += 256) {
        uint32_t dst;
        const float* src;
        if (i < 1024) {                       // A: 128 rows x 8 cp16 (gathered, tf32)
            int r = i >> 3, cc = i & 7;
            dst = sb + (uint32_t)r * (ROWF * 4) + (uint32_t)cc * 16;
            src = xt + (size_t)s_n[r] * D_ + k0 + cc * 4;
        } else {                              // B: 32 k-rows x 32 cp16 (direct experts)
            int j = i - 1024;
            int r = j >> 5, cc = j & 31;
            dst = sb + A_TILE_F + (uint32_t)r * (BF * 4) + (uint32_t)cc * 16;
            src = wb + (size_t)(k0 + r) * D_ + cc * 4;
        }
        cp16(dst, src);
    }
}

__global__ __launch_bounds__(256) void expert_gemm_mma(
    const float* __restrict__ experts, float* __restrict__ out) {
    extern __shared__ unsigned char dynsmem[];
    __shared__ int   s_n[128];
    __shared__ float s_v[128];
    __shared__ int   s_w[128];

    int bz = blockIdx.z;  int b = bz >> 3;  int e = bz & 7;
    int m0 = blockIdx.x * 128, f0 = blockIdx.y * 128;
    int tid = threadIdx.x, wid = tid >> 5, lane = tid & 31;
    int wm = wid & 1, wn = wid >> 1;   // warp tile: rows wm*64.., cols wn*32..

    uint32_t sbase = smem_u32(dynsmem);
    const uint32_t* smw = (const uint32_t*)dynsmem;

    if (tid < 128) {
        int o = bz * M_ + m0 + tid;
        int n = g_topk_idx[o];
        s_n[tid] = n;
        s_v[tid] = g_topk_val[o];
        s_w[tid] = (g_winner[b * N_ + n] == (m0 + tid) * E_ + e) ? 1 : 0;
    }
    __syncthreads();

    const float* xt = g_xt + (size_t)b * N_ * D_;
    const float* wb = experts + (size_t)e * D_ * D_ + f0;   // rows k, cols f0..f0+127

    float d[4][4][4];
#pragma unroll
    for (int i = 0; i < 4; i++)
#pragma unroll
        for (int j = 0; j < 4; j++)
#pragma unroll
            for (int q = 0; q < 4; q++) d[i][j][q] = 0.f;

    load_stage_t(sbase, 0, 0, tid, xt, wb, s_n);
    asm volatile("cp.async.commit_group;" ::: "memory");
    load_stage_t(sbase, 1, 32, tid, xt, wb, s_n);
    asm volatile("cp.async.commit_group;" ::: "memory");
    load_stage_t(sbase, 2, 64, tid, xt, wb, s_n);
    asm volatile("cp.async.commit_group;" ::: "memory");

    int qa = lane >> 2, ma = lane & 3;
    int buf = 0;

#pragma unroll 1
    for (int c = 0; c < 32; c++) {
        if (c >= 30) asm volatile("cp.async.wait_group 0;" ::: "memory");
        else         asm volatile("cp.async.wait_group 2;" ::: "memory");
        __syncthreads();

        const uint32_t* sbA = smw + (size_t)buf * (STAGE_F / 4);
        const uint32_t* sbB = sbA + A_TILE_F / 4;
#pragma unroll
        for (int kk = 0; kk < 32; kk += 8) {
            uint32_t afr[4][4], bfr[4][2];
#pragma unroll
            for (int mt = 0; mt < 4; mt++) {
                int r0 = wm * 64 + mt * 16 + qa;
                afr[mt][0] = sbA[r0 * ROWF + kk + ma];
                afr[mt][1] = sbA[(r0 + 8) * ROWF + kk + ma];
                afr[mt][2] = sbA[r0 * ROWF + kk + ma + 4];
                afr[mt][3] = sbA[(r0 + 8) * ROWF + kk + ma + 4];
            }
#pragma unroll
            for (int nt = 0; nt < 4; nt++) {
                int fc = wn * 32 + nt * 8 + qa;
                bfr[nt][0] = sbB[(kk + ma) * BF + fc];
                bfr[nt][1] = sbB[(kk + ma + 4) * BF + fc];
            }
#pragma unroll
            for (int mt = 0; mt < 4; mt++)
#pragma unroll
                for (int nt = 0; nt < 4; nt++) mma_tf32(d[mt][nt], afr[mt], bfr[nt]);
        }
        __syncthreads();
        if (c < 29) {
            load_stage_t(sbase, buf, (c + 3) * 32, tid, xt, wb, s_n);
            asm volatile("cp.async.commit_group;" ::: "memory");
        }
        buf = (buf == 2) ? 0 : buf + 1;
    }

    // epilogue: scale by gate value, winner-gated scatter
#pragma unroll
    for (int mt = 0; mt < 4; mt++) {
        int rbase = wm * 64 + mt * 16 + qa;
#pragma unroll
        for (int half = 0; half < 2; half++) {
            int r = rbase + half * 8;
            if (s_w[r]) {
                float sv = s_v[r];
                float* orow = out + ((size_t)b * N_ + s_n[r]) * D_ + f0 + wn * 32 + ma * 2;
#pragma unroll
                for (int nt = 0; nt < 4; nt++) {
                    float2 v;
                    v.x = d[mt][nt][half * 2 + 0] * sv;
                    v.y = d[mt][nt][half * 2 + 1] * sv;
                    *(float2*)(orow + nt * 8) = v;
                }
            }
        }
    }
}

// ========== k5: zero only unrouted rows ==========
__global__ void zero_unrouted_kernel(float4* __restrict__ out) {
    int row = blockIdx.x;
    if (g_winner[row] >= 0) return;
    out[(size_t)row * (D_ / 4) + threadIdx.x] = make_float4(0.f, 0.f, 0.f, 0.f);
}

// ---------------- launch ----------------
extern "C" void kernel_launch(void* const* d_in, const int* in_sizes, int n_in,
                              void* d_out, int out_size) {
    const float* x       = (const float*)d_in[0];
    const float* gw      = (const float*)d_in[1];
    const float* experts = (const float*)d_in[2];
    float* out = (float*)d_out;

    cudaFuncSetAttribute(sinkhorn_kernel, cudaFuncAttributeMaxDynamicSharedMemorySize,
                         (8 * SROW + N_) * (int)sizeof(float));
    cudaFuncSetAttribute(expert_gemm_mma, cudaFuncAttributeMaxDynamicSharedMemorySize,
                         3 * STAGE_F);

    gate_fused_kernel<<<(B_ * N_) / 8, 256>>>(x, gw);
    sinkhorn_kernel<<<B_, 1024, (8 * SROW + N_) * sizeof(float)>>>();
    topk_winner_kernel<<<B_ * E_, 1024>>>();
    expert_gemm_mma<<<dim3(M_ / 128, D_ / 128, B_ * E_), 256, 3 * STAGE_F>>>(experts, out);
    zero_unrouted_kernel<<<B_ * N_, 256>>>((float4*)out);
}

// round 9
// speedup vs baseline: 1.2415x; 1.0720x over previous
#include <cuda_runtime.h>
#include <cuda_bf16.h>
#include <math.h>
#include <stdint.h>

#define B_ 4
#define N_ 4096
#define D_ 1024
#define E_ 8
#define M_ 512   // N/E tokens per expert

// ---------------- scratch (device globals; no allocation allowed) ----------------
__device__ float g_t[B_ * N_ * E_];         // log(clamp(gate logits)) [b][n][e]
__device__ float g_r[B_ * N_];              // sinkhorn row (token) offsets
__device__ float g_c[B_ * E_];              // sinkhorn col (expert) offsets
__device__ int   g_topk_idx[B_ * E_ * M_];  // sorted token indices per (b,e), descending gate
__device__ float g_topk_val[B_ * E_ * M_];  // matching gate values
__device__ int   g_winner[B_ * N_];         // per-token winning key m*E+e (last-wins), -1 if unrouted

__device__ float g_xt[B_ * N_ * D_];        // tf32(x), RNA-rounded

// sinkhorn cross-block state
__device__ float2 g_part[2][B_][8][E_];     // [parity][b][seg][e] = (max, sum)
__device__ int    g_sbar;                   // grid barrier counter (reset by k1)

__device__ __forceinline__ uint32_t smem_u32(const void* p) {
    uint32_t a;
    asm("{ .reg .u64 t; cvta.to.shared.u64 t, %1; cvt.u32.u64 %0, t; }" : "=r"(a) : "l"(p));
    return a;
}
__device__ __forceinline__ void cp16(uint32_t dst, const void* src) {
    asm volatile("cp.async.cg.shared.global [%0], [%1], 16;" :: "r"(dst), "l"(src));
}
__device__ __forceinline__ uint32_t f2tf32(float f) {
    uint32_t u;
    asm("cvt.rna.tf32.f32 %0, %1;" : "=r"(u) : "f"(f));
    return u;
}
__device__ __forceinline__ void ldsm4(uint32_t* r, uint32_t addr) {
    asm volatile("ldmatrix.sync.aligned.m8n8.x4.shared.b16 {%0,%1,%2,%3}, [%4];"
                 : "=r"(r[0]), "=r"(r[1]), "=r"(r[2]), "=r"(r[3]) : "r"(addr));
}
__device__ __forceinline__ void mma_tf32(float* d, const uint32_t* a, const uint32_t* b) {
    asm volatile(
        "mma.sync.aligned.m16n8k8.row.col.f32.tf32.tf32.f32 "
        "{%0,%1,%2,%3}, {%4,%5,%6,%7}, {%8,%9}, {%0,%1,%2,%3};"
        : "+f"(d[0]), "+f"(d[1]), "+f"(d[2]), "+f"(d[3])
        : "r"(a[0]), "r"(a[1]), "r"(a[2]), "r"(a[3]), "r"(b[0]), "r"(b[1]));
}
__device__ __forceinline__ void bar_arrive(int* p) {
    asm volatile("red.release.gpu.global.add.s32 [%0], 1;" :: "l"(p) : "memory");
}
__device__ __forceinline__ int bar_ld(const int* p) {
    int v;
    asm volatile("ld.acquire.gpu.global.s32 %0, [%1];" : "=r"(v) : "l"(p) : "memory");
    return v;
}

// ========== k1: gate logits (+log clamp) + convert x->tf32 + winner init + barrier reset ==========
__global__ __launch_bounds__(256) void gate_fused_kernel(
    const float* __restrict__ x, const float* __restrict__ gw) {
    __shared__ float sw[E_ * D_];   // gate weights transposed [e][d]
    int tid = threadIdx.x;
    for (int i = tid; i < D_ * E_; i += 256) {
        int d = i / E_, e = i % E_;
        sw[e * D_ + d] = gw[i];
    }
    if (blockIdx.x < (B_ * N_) / 256)
        g_winner[blockIdx.x * 256 + tid] = -1;
    if (blockIdx.x == 0 && tid == 0) g_sbar = 0;
    __syncthreads();

    int warp = tid >> 5, lane = tid & 31;
    int row = blockIdx.x * 8 + warp;
    const float* xr = x + (size_t)row * D_;
    uint32_t* xo = (uint32_t*)(g_xt + (size_t)row * D_);
    float acc[E_];
#pragma unroll
    for (int e = 0; e < E_; e++) acc[e] = 0.f;
    for (int d = lane; d < D_; d += 32) {
        float xv = xr[d];
        xo[d] = f2tf32(xv);
#pragma unroll
        for (int e = 0; e < E_; e++) acc[e] += xv * sw[e * D_ + d];
    }
#pragma unroll
    for (int e = 0; e < E_; e++) {
#pragma unroll
        for (int off = 16; off; off >>= 1)
            acc[e] += __shfl_xor_sync(0xFFFFFFFFu, acc[e], off);
    }
    if (lane == 0) {
#pragma unroll
        for (int e = 0; e < E_; e++)
            g_t[(size_t)row * E_ + e] = logf(fmaxf(acc[e], 1e-6f));
    }
}

// ========== k2: distributed Sinkhorn, 32 blocks (b,seg), grid barriers ==========
#define SEG_TOK 512
#define SP 520
__global__ __launch_bounds__(1024) void sinkhorn_kernel() {
    __shared__ float st[E_ * SP];     // this segment's logits [e][tok]
    __shared__ float sr[SEG_TOK];
    __shared__ float s_pm[32], s_ps[32], s_c[E_];

    int blk = blockIdx.x;             // 0..31
    int b = blk >> 3, seg = blk & 7;
    int n0 = seg * SEG_TOK;
    int tid = threadIdx.x;

    const float* tb = g_t + ((size_t)b * N_ + n0) * E_;
    for (int i = tid; i < SEG_TOK * E_; i += 1024) {
        int n = i >> 3, e = i & 7;
        st[e * SP + n] = tb[i];
    }
    if (tid < SEG_TOK) sr[tid] = 0.f;
    __syncthreads();

    int warp = tid >> 5, lane = tid & 31;
    int e_w = warp & 7, sub = warp >> 3;   // 4 warps per expert, 128 tokens per warp

    for (int it = 0; it < 8; it++) {
        // ---- col partial over this block's 512 tokens ----
        const float* se = st + e_w * SP;
        int base = sub * 128 + lane;
        float m = -INFINITY;
#pragma unroll
        for (int k = 0; k < 4; k++) m = fmaxf(m, se[base + k * 32] - sr[base + k * 32]);
#pragma unroll
        for (int off = 16; off; off >>= 1)
            m = fmaxf(m, __shfl_xor_sync(0xFFFFFFFFu, m, off));
        float s = 0.f;
#pragma unroll
        for (int k = 0; k < 4; k++) s += __expf(se[base + k * 32] - sr[base + k * 32] - m);
#pragma unroll
        for (int off = 16; off; off >>= 1)
            s += __shfl_xor_sync(0xFFFFFFFFu, s, off);
        if (lane == 0) { s_pm[warp] = m; s_ps[warp] = s; }
        __syncthreads();
        if (tid < E_) {
            float mm = fmaxf(fmaxf(s_pm[tid], s_pm[8 + tid]), fmaxf(s_pm[16 + tid], s_pm[24 + tid]));
            float ss = 0.f;
#pragma unroll
            for (int q = 0; q < 4; q++) ss += s_ps[q * 8 + tid] * __expf(s_pm[q * 8 + tid] - mm);
            g_part[it & 1][b][seg][tid] = make_float2(mm, ss);
            __threadfence();
        }
        __syncthreads();
        // ---- grid barrier #it ----
        if (tid == 0) {
            bar_arrive(&g_sbar);
            int target = 32 * (it + 1);
            while (bar_ld(&g_sbar) < target) {}
        }
        __syncthreads();
        // ---- merge 8 segment partials (fixed order -> deterministic) ----
        if (tid < E_) {
            float mm = -INFINITY, ss = 0.f;
#pragma unroll
            for (int sg = 0; sg < 8; sg++) {
                float2 p = g_part[it & 1][b][sg][tid];
                float nm = fmaxf(mm, p.x);
                ss = ss * __expf(mm - nm) + p.y * __expf(p.x - nm);
                mm = nm;
            }
            s_c[tid] = mm + __logf(ss);
        }
        __syncthreads();
        // ---- row phase (local): sr[n] = LSE_e(st[e][n] - c_e) ----
        if (tid < SEG_TOK) {
            int n = tid;
            float v0 = st[0 * SP + n] - s_c[0], v1 = st[1 * SP + n] - s_c[1];
            float v2 = st[2 * SP + n] - s_c[2], v3 = st[3 * SP + n] - s_c[3];
            float v4 = st[4 * SP + n] - s_c[4], v5 = st[5 * SP + n] - s_c[5];
            float v6 = st[6 * SP + n] - s_c[6], v7 = st[7 * SP + n] - s_c[7];
            float mm = fmaxf(fmaxf(fmaxf(v0, v1), fmaxf(v2, v3)),
                             fmaxf(fmaxf(v4, v5), fmaxf(v6, v7)));
            float ss = __expf(v0 - mm) + __expf(v1 - mm) + __expf(v2 - mm) + __expf(v3 - mm)
                     + __expf(v4 - mm) + __expf(v5 - mm) + __expf(v6 - mm) + __expf(v7 - mm);
            sr[n] = mm + __logf(ss);
        }
        __syncthreads();
    }
    if (tid < SEG_TOK) g_r[b * N_ + n0 + tid] = sr[tid];
    if (seg == 0 && tid < E_) g_c[b * E_ + tid] = s_c[tid];
}

// ========== k3: top-512 sort per (b,e) + winner scatter ==========
__global__ __launch_bounds__(1024) void topk_winner_kernel() {
    __shared__ unsigned long long keys[N_];
    int b = blockIdx.x >> 3, e = blockIdx.x & 7;
    int tid = threadIdx.x;
    const float* tb = g_t + (size_t)b * N_ * E_ + e;
    const float* rb = g_r + (size_t)b * N_;
    float ce = g_c[b * E_ + e];

    for (int i = tid; i < N_; i += 1024) {
        float v = tb[(size_t)i * E_] - rb[i];
        unsigned int u = __float_as_uint(v);
        u = (u & 0x80000000u) ? ~u : (u | 0x80000000u);
        keys[i] = ((unsigned long long)u << 32) | (unsigned int)(N_ - 1 - i);
    }
    __syncthreads();
    for (int k = 2; k <= N_; k <<= 1) {
        for (int j = k >> 1; j > 0; j >>= 1) {
            for (int i = tid; i < N_; i += 1024) {
                int l = i ^ j;
                if (l > i) {
                    unsigned long long a = keys[i], c = keys[l];
                    bool desc = ((i & k) == 0);
                    if (desc ? (a < c) : (a > c)) { keys[i] = c; keys[l] = a; }
                }
            }
            __syncthreads();
        }
    }
    for (int m = tid; m < M_; m += 1024) {
        unsigned long long K = keys[m];
        int n = (N_ - 1) - (int)(unsigned int)(K & 0xFFFFFFFFull);
        int o = (b * E_ + e) * M_ + m;
        g_topk_idx[o] = n;
        g_topk_val[o] = expf(tb[(size_t)n * E_] - rb[n] - ce);
        atomicMax(&g_winner[b * N_ + n], m * E_ + e);
    }
}

// ========== k4: tf32 mma.sync gathered expert GEMM (PROFILED LAUNCH) ==========
// CTA tile 128(m) x 128(f); 8 warps in 2x4 of 64x32; BK=32, 3-stage cp.async.
// A smem: [m-row][k], pitch 36 floats (144 B, 16B-aligned rows -> ldmatrix).
// B smem: [k-row][f], pitch 136 floats (direct from experts).
#define ROWF 36
#define BF   136
#define A_TILE_F (128 * ROWF * 4)        // 18432 B
#define B_TILE_F (32 * BF * 4)           // 17408 B
#define STAGE_F (A_TILE_F + B_TILE_F)    // 35840 B

__device__ __forceinline__ void load_stage_t(
    uint32_t sbase, int buf, int k0, int tid,
    const float* __restrict__ xt, const float* __restrict__ wb, const int* s_n)
{
    uint32_t sb = sbase + (uint32_t)buf * STAGE_F;
#pragma unroll
    for (int i = tid; i < 2048; i += 256) {
        uint32_t dst;
        const float* src;
        if (i < 1024) {                       // A: 128 rows x 8 cp16 (gathered, tf32)
            int r = i >> 3, cc = i & 7;
            dst = sb + (uint32_t)r * (ROWF * 4) + (uint32_t)cc * 16;
            src = xt + (size_t)s_n[r] * D_ + k0 + cc * 4;
        } else {                              // B: 32 k-rows x 32 cp16 (direct experts)
            int j = i - 1024;
            int r = j >> 5, cc = j & 31;
            dst = sb + A_TILE_F + (uint32_t)r * (BF * 4) + (uint32_t)cc * 16;
            src = wb + (size_t)(k0 + r) * D_ + cc * 4;
        }
        cp16(dst, src);
    }
}

__global__ __launch_bounds__(256) void expert_gemm_mma(
    const float* __restrict__ experts, float* __restrict__ out) {
    extern __shared__ unsigned char dynsmem[];
    __shared__ int   s_n[128];
    __shared__ float s_v[128];
    __shared__ int   s_w[128];

    int bz = blockIdx.z;  int b = bz >> 3;  int e = bz & 7;
    int m0 = blockIdx.x * 128, f0 = blockIdx.y * 128;
    int tid = threadIdx.x, wid = tid >> 5, lane = tid & 31;
    int wm = wid & 1, wn = wid >> 1;   // warp tile: rows wm*64.., cols wn*32..

    uint32_t sbase = smem_u32(dynsmem);
    const uint32_t* smw = (const uint32_t*)dynsmem;

    if (tid < 128) {
        int o = bz * M_ + m0 + tid;
        int n = g_topk_idx[o];
        s_n[tid] = n;
        s_v[tid] = g_topk_val[o];
        s_w[tid] = (g_winner[b * N_ + n] == (m0 + tid) * E_ + e) ? 1 : 0;
    }
    __syncthreads();

    const float* xt = g_xt + (size_t)b * N_ * D_;
    const float* wb = experts + (size_t)e * D_ * D_ + f0;

    float d[4][4][4];
#pragma unroll
    for (int i = 0; i < 4; i++)
#pragma unroll
        for (int j = 0; j < 4; j++)
#pragma unroll
            for (int q = 0; q < 4; q++) d[i][j][q] = 0.f;

    load_stage_t(sbase, 0, 0, tid, xt, wb, s_n);
    asm volatile("cp.async.commit_group;" ::: "memory");
    load_stage_t(sbase, 1, 32, tid, xt, wb, s_n);
    asm volatile("cp.async.commit_group;" ::: "memory");
    load_stage_t(sbase, 2, 64, tid, xt, wb, s_n);
    asm volatile("cp.async.commit_group;" ::: "memory");

    int qa = lane >> 2, ma = lane & 3;
    int arow = lane & 15;                 // ldmatrix row-within-16 for this lane
    int acol = (lane >> 4) << 2;          // 0 or 4 (tf32 col group)
    int buf = 0;

#pragma unroll 1
    for (int c = 0; c < 32; c++) {
        if (c >= 30) asm volatile("cp.async.wait_group 0;" ::: "memory");
        else         asm volatile("cp.async.wait_group 2;" ::: "memory");
        __syncthreads();

        uint32_t abase = sbase + (uint32_t)buf * STAGE_F;
        const uint32_t* sbB = smw + (size_t)buf * (STAGE_F / 4) + A_TILE_F / 4;
#pragma unroll
        for (int kk = 0; kk < 32; kk += 8) {
            uint32_t afr[4][4], bfr[4][2];
#pragma unroll
            for (int mt = 0; mt < 4; mt++) {
                uint32_t ad = abase + (uint32_t)(wm * 64 + mt * 16 + arow) * (ROWF * 4)
                                    + (uint32_t)(kk + acol) * 4;
                ldsm4(afr[mt], ad);
            }
#pragma unroll
            for (int nt = 0; nt < 4; nt++) {
                int fc = wn * 32 + nt * 8 + qa;
                bfr[nt][0] = sbB[(kk + ma) * BF + fc];
                bfr[nt][1] = sbB[(kk + ma + 4) * BF + fc];
            }
#pragma unroll
            for (int mt = 0; mt < 4; mt++)
#pragma unroll
                for (int nt = 0; nt < 4; nt++) mma_tf32(d[mt][nt], afr[mt], bfr[nt]);
        }
        __syncthreads();
        if (c < 29) {
            load_stage_t(sbase, buf, (c + 3) * 32, tid, xt, wb, s_n);
            asm volatile("cp.async.commit_group;" ::: "memory");
        }
        buf = (buf == 2) ? 0 : buf + 1;
    }

    // epilogue: scale by gate value, winner-gated scatter
#pragma unroll
    for (int mt = 0; mt < 4; mt++) {
        int rbase = wm * 64 + mt * 16 + qa;
#pragma unroll
        for (int half = 0; half < 2; half++) {
            int r = rbase + half * 8;
            if (s_w[r]) {
                float sv = s_v[r];
                float* orow = out + ((size_t)b * N_ + s_n[r]) * D_ + f0 + wn * 32 + ma * 2;
#pragma unroll
                for (int nt = 0; nt < 4; nt++) {
                    float2 v;
                    v.x = d[mt][nt][half * 2 + 0] * sv;
                    v.y = d[mt][nt][half * 2 + 1] * sv;
                    *(float2*)(orow + nt * 8) = v;
                }
            }
        }
    }
}

// ========== k5: zero only unrouted rows ==========
__global__ void zero_unrouted_kernel(float4* __restrict__ out) {
    int row = blockIdx.x;
    if (g_winner[row] >= 0) return;
    out[(size_t)row * (D_ / 4) + threadIdx.x] = make_float4(0.f, 0.f, 0.f, 0.f);
}

// ---------------- launch ----------------
extern "C" void kernel_launch(void* const* d_in, const int* in_sizes, int n_in,
                              void* d_out, int out_size) {
    const float* x       = (const float*)d_in[0];
    const float* gw      = (const float*)d_in[1];
    const float* experts = (const float*)d_in[2];
    float* out = (float*)d_out;

    cudaFuncSetAttribute(expert_gemm_mma, cudaFuncAttributeMaxDynamicSharedMemorySize,
                         3 * STAGE_F);

    gate_fused_kernel<<<(B_ * N_) / 8, 256>>>(x, gw);
    sinkhorn_kernel<<<B_ * 8, 1024>>>();
    topk_winner_kernel<<<B_ * E_, 1024>>>();
    expert_gemm_mma<<<dim3(M_ / 128, D_ / 128, B_ * E_), 256, 3 * STAGE_F>>>(experts, out);
    zero_unrouted_kernel<<<B_ * N_, 256>>>((float4*)out);
}